// round 17
// baseline (speedup 1.0000x reference)
#include <cuda_runtime.h>
#include <cuda_fp16.h>
#include <cstdint>

#define B_ 1024
#define T_ 128

typedef unsigned short u16;
typedef uint32_t u32;

// ---------------- static device buffers (fp16, single-term weights) ----------------
__device__ __align__(16) u16 W1h[512 * 1024];
__device__ __align__(16) u16 W3h[512 * 1024];
__device__ __align__(16) u16 Wgh[2048 * 1024];   // [p=4i+q][k over x|h]
__device__ __align__(16) u16 Hh[2][B_ * 512];
__device__ __align__(16) u16 Ch[B_ * 512];
__device__ __align__(16) u16 Z1h[B_ * 512];
__device__ __align__(16) u16 Xh[B_ * 512];
__device__ __align__(16) u16 Z2h[(size_t)T_ * B_ * 512];
__device__ float g_c[B_ * 512];     // fp32 master cell state
__device__ float g_bgp[2048];

// ---------------- helpers ----------------
__device__ __forceinline__ u32 swz(u32 o) { return o ^ ((o >> 3) & 0x70); }
__device__ __forceinline__ u32 s2u(const void* p) {
    u32 a;
    asm("{ .reg .u64 t; cvta.to.shared.u64 t, %1; cvt.u32.u64 %0, t; }" : "=r"(a) : "l"(p));
    return a;
}
__device__ __forceinline__ void cp16(u32 dst, const void* src) {
    asm volatile("cp.async.cg.shared.global [%0], [%1], 16;" :: "r"(dst), "l"(src));
}
__device__ __forceinline__ void cp_commit() { asm volatile("cp.async.commit_group;" ::: "memory"); }
template <int N> __device__ __forceinline__ void cp_wait() {
    asm volatile("cp.async.wait_group %0;" :: "n"(N) : "memory");
}
__device__ __forceinline__ void ldsm4(u32* r, u32 a) {
    asm volatile("ldmatrix.sync.aligned.m8n8.x4.shared.b16 {%0,%1,%2,%3}, [%4];"
                 : "=r"(r[0]), "=r"(r[1]), "=r"(r[2]), "=r"(r[3]) : "r"(a));
}
__device__ __forceinline__ void hmma(float* c, const u32* a, u32 b0, u32 b1) {
    asm volatile("mma.sync.aligned.m16n8k16.row.col.f32.f16.f16.f32 "
                 "{%0,%1,%2,%3}, {%4,%5,%6,%7}, {%8,%9}, {%0,%1,%2,%3};"
                 : "+f"(c[0]), "+f"(c[1]), "+f"(c[2]), "+f"(c[3])
                 : "r"(a[0]), "r"(a[1]), "r"(a[2]), "r"(a[3]), "r"(b0), "r"(b1));
}
__device__ __forceinline__ u16 h1(float v) {
    __half x = __float2half_rn(v);
    return *(u16*)&x;
}
__device__ __forceinline__ u32 pack2h(float a, float b) {
    __half2 p = __floats2half2_rn(a, b);
    return *(u32*)&p;
}
__device__ __forceinline__ float sigf(float x) { return 1.f / (1.f + expf(-x)); }

// ---------------- prep: fp16 weights, biases, zero state ----------------
__global__ __launch_bounds__(256) void prep_w(
    const float* __restrict__ W1, const float* __restrict__ W3,
    const float* __restrict__ Wih, const float* __restrict__ Whh,
    const float* __restrict__ bih, const float* __restrict__ bhh)
{
    const int N1 = 524288, N2 = 1048576, N3 = N2 + 2097152;
    const int N4 = N3 + 2048, N5 = N4 + 524288, N6 = N5 + 524288;
    for (int idx = blockIdx.x * blockDim.x + threadIdx.x; idx < N6;
         idx += gridDim.x * blockDim.x) {
        if (idx < N2) {
            int j = (idx < N1) ? idx : idx - N1;
            float v = (idx < N1) ? W1[j] : W3[j];
            if (idx < N1) W1h[j] = h1(v); else W3h[j] = h1(v);
        } else if (idx < N3) {
            int j = idx - N2;
            int p = j >> 10, k = j & 1023;
            int r = (p & 3) * 512 + (p >> 2);
            float v = (k < 512) ? Wih[r * 512 + k] : Whh[r * 512 + (k - 512)];
            Wgh[j] = h1(v);
        } else if (idx < N4) {
            int p = idx - N3, i = p >> 2, q = p & 3;
            g_bgp[p] = bih[q * 512 + i] + bhh[q * 512 + i];
        } else if (idx < N5) {
            int j = idx - N4;
            int sel = j >> 18, w = j & 262143;
            u16* b = (sel == 0) ? Hh[0] : Ch;
            *(u32*)&b[w * 2] = 0u;
        } else g_c[idx - N5] = 0.f;
    }
}

// ---------------- prep: z2 for all t (fp16) ----------------
__global__ __launch_bounds__(256) void prep_z2(
    const float* __restrict__ sv, const float* __restrict__ W2, const float* __restrict__ b2)
{
    __shared__ float W2s[10 * 512];
    __shared__ float svs[32 * 10];
    int tid = threadIdx.x;
    for (int idx = tid; idx < 5120; idx += 256)
        W2s[(idx % 10) * 512 + idx / 10] = W2[idx];
    int u0 = blockIdx.x * 32;
    for (int idx = tid; idx < 320; idx += 256) svs[idx] = sv[u0 * 10 + idx];
    __syncthreads();
    int f0 = tid * 2;
    float c0 = b2[f0], c1 = b2[f0 + 1];
    for (int p = 0; p < 32; ++p) {
        int u = u0 + p, bb = u >> 7, tt = u & 127;
        float a0 = c0, a1 = c1;
#pragma unroll
        for (int j = 0; j < 10; ++j) {
            float s = svs[p * 10 + j];
            a0 += s * W2s[j * 512 + f0];
            a1 += s * W2s[j * 512 + f0 + 1];
        }
        size_t off = (size_t)tt * 524288 + (size_t)bb * 512 + f0;
        *(u32*)&Z2h[off] = pack2h(fmaxf(a0, 0.f), fmaxf(a1, 0.f));
    }
}

// ---------------- single-term fp16 HMMA, K=128/stage, traffic-minimal tiles ----------------
// MODE 0: z1 = relu([h|c] @ W1^T + b1)      tile 64x64,  grid (16,8)
// MODE 1: x  = relu([z1|z2_t] @ W3^T + b3)  tile 64x64,  grid (16,8)
// MODE 2: gates(interleaved) + LSTM cell    tile 128x128, grid (8,16)
template <int MODE>
__global__ __launch_bounds__(256, 1) void gemm_mma(
    int ping, int t, const float* __restrict__ bias, float* __restrict__ out)
{
    constexpr int MT  = (MODE == 2) ? 128 : 64;
    constexpr int NT  = (MODE == 2) ? 128 : 64;
    constexpr int TH  = 256;
    constexpr int WMW = (MODE == 2) ? 4 : 2;
    constexpr int WNW = 8 / WMW;
    constexpr int NFR = (NT / 8) / WNW;          // MODE2: 8, else 2
    constexpr int NSTAGE = (MODE == 2) ? 2 : 3;
    constexpr u32 A_IMG = MT * 128;
    constexpr u32 B_IMG = NT * 128;
    constexpr u32 OB = 2 * A_IMG;
    constexpr u32 STAGE = 2 * A_IMG + 2 * B_IMG;

    extern __shared__ __align__(16) unsigned char smem[];
    const u32 sb = s2u(smem);
    const int tid = threadIdx.x, lane = tid & 31, wid = tid >> 5;
    const int m0 = blockIdx.x * MT, n0 = blockIdx.y * NT;
    const int wm = wid % WMW, wn = wid / WMW;

    const u16 *A1, *A2, *Wh;
    if (MODE == 0) { A1 = Hh[ping]; A2 = Ch; Wh = W1h; }
    else if (MODE == 1) {
        A1 = Z1h; A2 = Z2h + (size_t)t * 524288; Wh = W3h;
    } else { A1 = Xh; A2 = Hh[ping]; Wh = Wgh; }

    float acc[2][NFR][4];
#pragma unroll
    for (int a = 0; a < 2; ++a)
#pragma unroll
        for (int b = 0; b < NFR; ++b)
#pragma unroll
            for (int q = 0; q < 4; ++q) acc[a][b][q] = 0.f;

    // stage s covers k in [s*128, s*128+128): two 64-k half-images each for A and B
    auto load_stage = [&](int s) {
        int buf = s % NSTAGE, k0 = s * 128;
        u32 base = sb + (u32)buf * STAGE;
#pragma unroll
        for (int i = tid; i < MT * 16; i += TH) {
            int row = i >> 4, q = i & 15, half = q >> 3, c16 = q & 7;
            int ks = k0 + half * 64;
            const u16* sa = (ks < 512) ? A1 : A2;
            cp16(base + (u32)half * A_IMG + swz((u32)(row * 128 + c16 * 16)),
                 sa + (size_t)(m0 + row) * 512 + (ks & 511) + c16 * 8);
        }
#pragma unroll
        for (int i = tid; i < NT * 16; i += TH) {
            int row = i >> 4, q = i & 15, half = q >> 3, c16 = q & 7;
            cp16(base + OB + (u32)half * B_IMG + swz((u32)(row * 128 + c16 * 16)),
                 Wh + (size_t)(n0 + row) * 1024 + k0 + half * 64 + c16 * 8);
        }
    };

#pragma unroll
    for (int s = 0; s < NSTAGE - 1; ++s) { load_stage(s); cp_commit(); }

    const int arow = wm * 32 + (lane & 15);
    const int brow = wn * (NFR * 8) + (lane & 15);
    const u32 hi16 = (u32)((lane >> 4) * 16);

    for (int s = 0; s < 8; ++s) {
        cp_wait<NSTAGE - 2>();
        __syncthreads();
        if (s + NSTAGE - 1 < 8) load_stage(s + NSTAGE - 1);
        cp_commit();   // unconditional: tail-drain-safe group alignment
        u32 base = sb + (u32)(s % NSTAGE) * STAGE;

        if (MODE == 2) {
#pragma unroll
            for (int kk = 0; kk < 8; ++kk) {
                u32 Ab = base + (u32)(kk >> 2) * A_IMG;
                u32 Bb = base + OB + (u32)(kk >> 2) * B_IMG;
                u32 kb = (u32)((kk & 3) * 32) + hi16;
                u32 Ar[2][4], Br[4][4];
#pragma unroll
                for (int fm = 0; fm < 2; ++fm)
                    ldsm4(Ar[fm], Ab + swz((u32)((arow + fm * 16) * 128) + kb));
#pragma unroll
                for (int nf = 0; nf < 4; ++nf)
                    ldsm4(Br[nf], Bb + swz((u32)((brow + nf * 16) * 128) + kb));
#pragma unroll
                for (int fm = 0; fm < 2; ++fm)
#pragma unroll
                    for (int fn = 0; fn < 8; ++fn)
                        hmma(acc[fm][fn], Ar[fm],
                             Br[fn >> 1][fn & 1], Br[fn >> 1][(fn & 1) + 2]);
            }
        } else {
            u32 Af[2][2][4], Bf[2][4];
#define LDFRAG(bf, kk) do { \
            u32 Ab_ = base + (u32)((kk) >> 2) * A_IMG; \
            u32 Bb_ = base + OB + (u32)((kk) >> 2) * B_IMG; \
            u32 kb = (u32)(((kk) & 3) * 32) + hi16; \
            ldsm4(Af[bf][0], Ab_ + swz((u32)(arow * 128) + kb)); \
            ldsm4(Af[bf][1], Ab_ + swz((u32)((arow + 16) * 128) + kb)); \
            ldsm4(Bf[bf], Bb_ + swz((u32)(brow * 128) + kb)); \
        } while (0)
            LDFRAG(0, 0);
#pragma unroll
            for (int kk = 0; kk < 8; ++kk) {
                const int cur = kk & 1;
                if (kk < 7) LDFRAG(cur ^ 1, kk + 1);
#pragma unroll
                for (int fm = 0; fm < 2; ++fm)
#pragma unroll
                    for (int fn = 0; fn < 2; ++fn)
                        hmma(acc[fm][fn], Af[cur][fm], Bf[cur][fn], Bf[cur][fn + 2]);
            }
#undef LDFRAG
        }
    }

    // ---------------- epilogue ----------------
    if (MODE < 2) {
        u16* Dh = (MODE == 0) ? Z1h : Xh;
#pragma unroll
        for (int fm = 0; fm < 2; ++fm)
#pragma unroll
            for (int fn = 0; fn < NFR; ++fn) {
                int c = n0 + wn * (NFR * 8) + fn * 8 + (lane & 3) * 2;
                int r = m0 + wm * 32 + fm * 16 + (lane >> 2);
                float b0 = bias[c], b1v = bias[c + 1];
                *(u32*)&Dh[(size_t)r * 512 + c] =
                    pack2h(fmaxf(acc[fm][fn][0] + b0, 0.f), fmaxf(acc[fm][fn][1] + b1v, 0.f));
                *(u32*)&Dh[(size_t)(r + 8) * 512 + c] =
                    pack2h(fmaxf(acc[fm][fn][2] + b0, 0.f), fmaxf(acc[fm][fn][3] + b1v, 0.f));
            }
    } else {
        u16* hh = Hh[ping ^ 1];
        bool odd = lane & 1;
#pragma unroll
        for (int fm = 0; fm < 2; ++fm)
#pragma unroll
            for (int fn = 0; fn < NFR; ++fn) {
                float v0 = acc[fm][fn][0], v1 = acc[fm][fn][1];
                float v2 = acc[fm][fn][2], v3 = acc[fm][fn][3];
                float s0 = __shfl_xor_sync(0xFFFFFFFFu, v0, 1);
                float s1 = __shfl_xor_sync(0xFFFFFFFFu, v1, 1);
                float s2 = __shfl_xor_sync(0xFFFFFFFFu, v2, 1);
                float s3 = __shfl_xor_sync(0xFFFFFFFFu, v3, 1);
                int p = n0 + wn * (NFR * 8) + fn * 8 + (lane & 3) * 2;
                int u = p >> 2;
                int row = m0 + wm * 32 + fm * 16 + (lane >> 2) + (odd ? 8 : 0);
                float gi = odd ? s2 : v0;
                float gf = odd ? s3 : v1;
                float gg = odd ? v2 : s0;
                float go = odd ? v3 : s1;
                int pb = u * 4;
                gi += g_bgp[pb];     gf += g_bgp[pb + 1];
                gg += g_bgp[pb + 2]; go += g_bgp[pb + 3];
                float I = sigf(gi), F = sigf(gf), G = tanhf(gg), O = sigf(go);
                size_t ix = (size_t)row * 512 + u;
                float cn = F * g_c[ix] + I * G;
                float hn = O * tanhf(cn);
                g_c[ix] = cn;
                out[((size_t)row * T_ + t) * 512 + u] = hn;
                hh[ix] = h1(hn);
                Ch[ix] = h1(cn);
            }
    }
}

// ---------------- launch: 3 full-batch kernels per step ----------------
extern "C" void kernel_launch(void* const* d_in, const int* in_sizes, int n_in,
                              void* d_out, int out_size)
{
    const float* sv  = (const float*)d_in[0];
    const float* W1  = (const float*)d_in[1];
    const float* b1  = (const float*)d_in[2];
    const float* W2  = (const float*)d_in[3];
    const float* b2  = (const float*)d_in[4];
    const float* W3  = (const float*)d_in[5];
    const float* b3  = (const float*)d_in[6];
    const float* Wih = (const float*)d_in[7];
    const float* Whh = (const float*)d_in[8];
    const float* bih = (const float*)d_in[9];
    const float* bhh = (const float*)d_in[10];
    float* out = (float*)d_out;

    const int SM01 = 3 * (2 * 64 * 128 + 2 * 64 * 128);      // 3*32768 = 98304
    const int SM2  = 2 * (2 * 128 * 128 + 2 * 128 * 128);    // 2*65536 = 131072

    static bool init = false;
    if (!init) {
        init = true;
        cudaFuncSetAttribute(gemm_mma<0>, cudaFuncAttributeMaxDynamicSharedMemorySize, SM01);
        cudaFuncSetAttribute(gemm_mma<1>, cudaFuncAttributeMaxDynamicSharedMemorySize, SM01);
        cudaFuncSetAttribute(gemm_mma<2>, cudaFuncAttributeMaxDynamicSharedMemorySize, SM2);
    }

    prep_w<<<2048, 256>>>(W1, W3, Wih, Whh, bih, bhh);
    prep_z2<<<4096, 256>>>(sv, W2, b2);

    dim3 gs(16, 8), gg(8, 16);
    for (int t = 0; t < T_; ++t) {
        int ping = t & 1;
        gemm_mma<0><<<gs, 256, SM01>>>(ping, t, b1, out);
        gemm_mma<1><<<gs, 256, SM01>>>(ping, t, b3, out);
        gemm_mma<2><<<gg, 256, SM2>>>(ping, t, nullptr, out);
    }
}